// round 5
// baseline (speedup 1.0000x reference)
#include <cuda_runtime.h>
#include <cuda_bf16.h>

#define L 256
#define NPIX (4096 * 4096)

// Confusion matrix scratch (device global — no allocations allowed).
__device__ int g_C[L * L];

// ---------------------------------------------------------------------------
// Kernel 1: zero the confusion matrix (re-run every graph replay).
// ---------------------------------------------------------------------------
__global__ void zero_kernel() {
    int i = blockIdx.x * blockDim.x + threadIdx.x;
    if (i < L * L) g_C[i] = 0;
}

// ---------------------------------------------------------------------------
// Kernel 2: histogram. Each thread handles 4 pixels via int4 loads, then does
// 4 global atomicAdds (no return value -> REDG, no round-trip latency).
// ---------------------------------------------------------------------------
__global__ void hist_kernel(const int* __restrict__ pred,
                            const int* __restrict__ gt, int n4) {
    int i = blockIdx.x * blockDim.x + threadIdx.x;
    if (i >= n4) return;
    int4 p = reinterpret_cast<const int4*>(pred)[i];
    int4 g = reinterpret_cast<const int4*>(gt)[i];
    atomicAdd(&g_C[g.x * L + p.x], 1);
    atomicAdd(&g_C[g.y * L + p.y], 1);
    atomicAdd(&g_C[g.z * L + p.z], 1);
    atomicAdd(&g_C[g.w * L + p.w], 1);
}

// ---------------------------------------------------------------------------
// Kernel 3: reduction + greedy matching. One block, 256 threads.
// Thread t owns gt-row t and pred-column t of C. The final greedy match is a
// strictly sequential 255-step scan (matches jax.lax.scan order, including
// float accumulation order), done by thread 0.
// ---------------------------------------------------------------------------
__global__ void reduce_kernel(float* __restrict__ out) {
    __shared__ int sh_gt_size[L];
    __shared__ int sh_pred_size[L];
    __shared__ int sh_colcnt[L];    // # of gt>=1 rows with Cnz>0 in column t
    __shared__ int sh_best_p[L];
    __shared__ int sh_inter[L];
    __shared__ unsigned char sh_has[L];

    int t = threadIdx.x;  // 0..255

    // Row sum (full C, including column 0) — gt_size
    int rs = 0;
    #pragma unroll 8
    for (int p = 0; p < L; p++) rs += g_C[t * L + p];
    sh_gt_size[t] = rs;

    // Column sum (full C) — pred_size; simultaneously count Cnz>0 per column
    int cs = 0, cc = 0;
    #pragma unroll 8
    for (int g = 0; g < L; g++) {
        int v = g_C[g * L + t];
        cs += v;
        if (g > 0 && t > 0 && v > 0) cc++;
    }
    sh_pred_size[t] = cs;
    sh_colcnt[t] = (t > 0) ? cc : 0;
    __syncthreads();

    // Majority match per gt row: first p>=1 (Cnz) with 2*C[g][p] > gt_size[g].
    // (At most one pred can majority-cover a gt; argmax picks the first true.)
    int bp = 0, hv = 0, iv = 0;
    if (t > 0) {
        int gs = sh_gt_size[t];
        for (int p = 1; p < L; p++) {
            int v = g_C[t * L + p];
            if (2 * v > gs) { bp = p; hv = 1; iv = v; break; }
        }
    }
    sh_best_p[t] = bp;
    sh_has[t] = (unsigned char)hv;
    sh_inter[t] = iv;
    __syncthreads();

    if (t == 0) {
        int num_gt = 0, num_pred = 0, pairs = 0, ea = 0;
        for (int i = 1; i < L; i++) {
            if (sh_gt_size[i] > 0) num_gt++;
            if (sh_pred_size[i] > 0) num_pred++;
            pairs += sh_colcnt[i];
            if (sh_colcnt[i] > 1) ea++;
        }

        // Greedy matching in ascending gt-label order; a pred may match once.
        bool used[L];
        for (int i = 0; i < L; i++) used[i] = false;
        int tp = 0;
        float seg_sum = 0.0f;
        for (int g = 1; g < L; g++) {
            int pl = sh_best_p[g];
            bool ok = sh_has[g] && !used[pl];
            if (ok) {
                int uni = sh_gt_size[g] + sh_pred_size[pl] - sh_inter[g];
                if (uni < 1) uni = 1;
                seg_sum += (float)sh_inter[g] / (float)uni;
                used[pl] = true;
                tp++;
            }
        }

        int ngi = num_gt > 0 ? num_gt : 1;
        float ng = (float)ngi;
        float seg = seg_sum / ng;
        int ns = pairs - tp;
        int fn = num_gt - tp;
        int fp = num_pred - tp;
        float det = 1.0f - (float)(fp + fn + ns + ea) / ng;

        bool both_empty = (num_gt == 0) && (num_pred == 0);
        bool any_empty = (num_gt == 0) || (num_pred == 0);
        if (both_empty)      { seg = 1.0f; det = 1.0f; }
        else if (any_empty)  { seg = 0.0f; det = 0.0f; }

        out[0] = seg;
        out[1] = det;
    }
}

// ---------------------------------------------------------------------------
extern "C" void kernel_launch(void* const* d_in, const int* in_sizes, int n_in,
                              void* d_out, int out_size) {
    const int* pred = (const int*)d_in[0];  // pred_labels_mask
    const int* gt   = (const int*)d_in[1];  // gt_labels_mask
    float* out = (float*)d_out;

    int n = in_sizes[0];       // 16,777,216
    int n4 = n / 4;            // int4-vectorized count

    zero_kernel<<<(L * L + 255) / 256, 256>>>();
    hist_kernel<<<(n4 + 255) / 256, 256>>>(pred, gt, n4);
    reduce_kernel<<<1, L>>>(out);
}

// round 6
// speedup vs baseline: 2.1715x; 2.1715x over previous
#include <cuda_runtime.h>
#include <cuda_bf16.h>

#define L 256
#define NBINS (L * L)          // 65536 bins
#define NWORDS (NBINS / 2)     // 32768 uint32 words (2 x 16-bit counters each)
#define HIST_BLOCKS 152        // one 128KB-smem block per SM (GB300: 152 SMs)
#define HIST_THREADS 1024
#define SMEM_BYTES (NWORDS * 4)  // 131072

// Per-block private histograms (packed u16 pairs) — overwritten by stores
// every replay, so no zeroing kernel is needed.
__device__ unsigned int g_partials[HIST_BLOCKS * NWORDS];
// Final confusion matrix — fully overwritten by combine_kernel each replay.
__device__ int g_C[NBINS];

// ---------------------------------------------------------------------------
// Kernel 1: privatized histogram. Each block owns a full 65536-bin histogram
// in shared memory as packed 16-bit counters (128 KB). Pixels via int4 loads.
// ---------------------------------------------------------------------------
__global__ __launch_bounds__(HIST_THREADS, 1)
void hist_kernel(const int* __restrict__ pred,
                 const int* __restrict__ gt, int n4) {
    extern __shared__ unsigned int sh[];  // NWORDS

    // Zero the private histogram (32 stores/thread).
    #pragma unroll
    for (int i = threadIdx.x; i < NWORDS; i += HIST_THREADS) sh[i] = 0;
    __syncthreads();

    const int4* __restrict__ p4 = reinterpret_cast<const int4*>(pred);
    const int4* __restrict__ g4 = reinterpret_cast<const int4*>(gt);
    int stride = gridDim.x * blockDim.x;
    for (int i = blockIdx.x * blockDim.x + threadIdx.x; i < n4; i += stride) {
        int4 p = p4[i];
        int4 g = g4[i];
        int b0 = g.x * L + p.x;
        int b1 = g.y * L + p.y;
        int b2 = g.z * L + p.z;
        int b3 = g.w * L + p.w;
        atomicAdd(&sh[b0 >> 1], 1u << ((b0 & 1) << 4));
        atomicAdd(&sh[b1 >> 1], 1u << ((b1 & 1) << 4));
        atomicAdd(&sh[b2 >> 1], 1u << ((b2 & 1) << 4));
        atomicAdd(&sh[b3 >> 1], 1u << ((b3 & 1) << 4));
    }
    __syncthreads();

    // Flush private histogram to global (coalesced uint4 stores, no atomics).
    uint4* __restrict__ dst =
        reinterpret_cast<uint4*>(&g_partials[blockIdx.x * NWORDS]);
    const uint4* __restrict__ src = reinterpret_cast<const uint4*>(sh);
    #pragma unroll
    for (int i = threadIdx.x; i < NWORDS / 4; i += HIST_THREADS) dst[i] = src[i];
}

// ---------------------------------------------------------------------------
// Kernel 2: combine partials -> g_C. One thread per packed word; sums the
// lo/hi 16-bit halves across all HIST_BLOCKS partials. Fully overwrites g_C.
// ---------------------------------------------------------------------------
__global__ void combine_kernel() {
    int w = blockIdx.x * blockDim.x + threadIdx.x;
    if (w >= NWORDS) return;
    unsigned int lo = 0, hi = 0;
    #pragma unroll 8
    for (int k = 0; k < HIST_BLOCKS; k++) {
        unsigned int v = g_partials[k * NWORDS + w];
        lo += v & 0xFFFFu;
        hi += v >> 16;
    }
    reinterpret_cast<int2*>(g_C)[w] = make_int2((int)lo, (int)hi);
}

// ---------------------------------------------------------------------------
// Kernel 3: reduction + greedy matching. One block, 256 threads. Thread t
// owns gt-row t and pred-column t. Final 255-step greedy scan matches the
// jax.lax.scan order exactly (including float accumulation order).
// ---------------------------------------------------------------------------
__global__ void reduce_kernel(float* __restrict__ out) {
    __shared__ int sh_gt_size[L];
    __shared__ int sh_pred_size[L];
    __shared__ int sh_colcnt[L];
    __shared__ int sh_best_p[L];
    __shared__ int sh_inter[L];
    __shared__ unsigned char sh_has[L];

    int t = threadIdx.x;  // 0..255

    // Row sum (full C) — gt_size
    int rs = 0;
    #pragma unroll 8
    for (int p = 0; p < L; p++) rs += g_C[t * L + p];
    sh_gt_size[t] = rs;

    // Column sum (full C) — pred_size; count Cnz>0 per column
    int cs = 0, cc = 0;
    #pragma unroll 8
    for (int g = 0; g < L; g++) {
        int v = g_C[g * L + t];
        cs += v;
        if (g > 0 && t > 0 && v > 0) cc++;
    }
    sh_pred_size[t] = cs;
    sh_colcnt[t] = (t > 0) ? cc : 0;
    __syncthreads();

    // Majority match per gt row: first p>=1 with 2*C[g][p] > gt_size[g]
    // (at most one pred can majority-cover a gt).
    int bp = 0, hv = 0, iv = 0;
    if (t > 0) {
        int gs = sh_gt_size[t];
        for (int p = 1; p < L; p++) {
            int v = g_C[t * L + p];
            if (2 * v > gs) { bp = p; hv = 1; iv = v; break; }
        }
    }
    sh_best_p[t] = bp;
    sh_has[t] = (unsigned char)hv;
    sh_inter[t] = iv;
    __syncthreads();

    if (t == 0) {
        int num_gt = 0, num_pred = 0, pairs = 0, ea = 0;
        for (int i = 1; i < L; i++) {
            if (sh_gt_size[i] > 0) num_gt++;
            if (sh_pred_size[i] > 0) num_pred++;
            pairs += sh_colcnt[i];
            if (sh_colcnt[i] > 1) ea++;
        }

        // Greedy matching in ascending gt-label order; a pred matches once.
        bool used[L];
        for (int i = 0; i < L; i++) used[i] = false;
        int tp = 0;
        float seg_sum = 0.0f;
        for (int g = 1; g < L; g++) {
            int pl = sh_best_p[g];
            bool ok = sh_has[g] && !used[pl];
            if (ok) {
                int uni = sh_gt_size[g] + sh_pred_size[pl] - sh_inter[g];
                if (uni < 1) uni = 1;
                seg_sum += (float)sh_inter[g] / (float)uni;
                used[pl] = true;
                tp++;
            }
        }

        int ngi = num_gt > 0 ? num_gt : 1;
        float ng = (float)ngi;
        float seg = seg_sum / ng;
        int ns = pairs - tp;
        int fn = num_gt - tp;
        int fp = num_pred - tp;
        float det = 1.0f - (float)(fp + fn + ns + ea) / ng;

        bool both_empty = (num_gt == 0) && (num_pred == 0);
        bool any_empty = (num_gt == 0) || (num_pred == 0);
        if (both_empty)      { seg = 1.0f; det = 1.0f; }
        else if (any_empty)  { seg = 0.0f; det = 0.0f; }

        out[0] = seg;
        out[1] = det;
    }
}

// ---------------------------------------------------------------------------
extern "C" void kernel_launch(void* const* d_in, const int* in_sizes, int n_in,
                              void* d_out, int out_size) {
    const int* pred = (const int*)d_in[0];  // pred_labels_mask
    const int* gt   = (const int*)d_in[1];  // gt_labels_mask
    float* out = (float*)d_out;

    int n = in_sizes[0];  // 16,777,216
    int n4 = n / 4;

    // Opt in to 128 KB dynamic shared memory (host-side attribute set;
    // legal under graph capture, idempotent across calls).
    cudaFuncSetAttribute(hist_kernel,
                         cudaFuncAttributeMaxDynamicSharedMemorySize,
                         SMEM_BYTES);

    hist_kernel<<<HIST_BLOCKS, HIST_THREADS, SMEM_BYTES>>>(pred, gt, n4);
    combine_kernel<<<(NWORDS + 255) / 256, 256>>>();
    reduce_kernel<<<1, L>>>(out);
}

// round 7
// speedup vs baseline: 4.0837x; 1.8806x over previous
#include <cuda_runtime.h>
#include <cuda_bf16.h>

#define L 256
#define NBINS (L * L)          // 65536 bins
#define NWORDS (NBINS / 2)     // 32768 uint32 words (2 x 16-bit counters each)
#define HIST_BLOCKS 152        // one 128KB-smem block per SM (GB300: 152 SMs)
#define HIST_THREADS 1024
#define SMEM_BYTES (NWORDS * 4)  // 131072

// Per-block private histograms (packed u16 pairs) — fully overwritten by
// stores every replay, so no zeroing kernel is needed.
__device__ unsigned int g_partials[HIST_BLOCKS * NWORDS];
// Final confusion matrix — fully overwritten by combine_kernel each replay.
__device__ int g_C[NBINS];

// ---------------------------------------------------------------------------
// Kernel 1: privatized histogram. Each block owns a full 65536-bin histogram
// in shared memory as packed 16-bit counters (128 KB). Pixels via int4 loads.
// ---------------------------------------------------------------------------
__global__ __launch_bounds__(HIST_THREADS, 1)
void hist_kernel(const int* __restrict__ pred,
                 const int* __restrict__ gt, int n4) {
    extern __shared__ unsigned int sh[];  // NWORDS

    // Zero the private histogram.
    #pragma unroll
    for (int i = threadIdx.x; i < NWORDS; i += HIST_THREADS) sh[i] = 0;
    __syncthreads();

    const int4* __restrict__ p4 = reinterpret_cast<const int4*>(pred);
    const int4* __restrict__ g4 = reinterpret_cast<const int4*>(gt);
    int stride = gridDim.x * blockDim.x;
    for (int i = blockIdx.x * blockDim.x + threadIdx.x; i < n4; i += stride) {
        int4 p = p4[i];
        int4 g = g4[i];
        int b0 = g.x * L + p.x;
        int b1 = g.y * L + p.y;
        int b2 = g.z * L + p.z;
        int b3 = g.w * L + p.w;
        atomicAdd(&sh[b0 >> 1], 1u << ((b0 & 1) << 4));
        atomicAdd(&sh[b1 >> 1], 1u << ((b1 & 1) << 4));
        atomicAdd(&sh[b2 >> 1], 1u << ((b2 & 1) << 4));
        atomicAdd(&sh[b3 >> 1], 1u << ((b3 & 1) << 4));
    }
    __syncthreads();

    // Flush private histogram to global (coalesced uint4 stores, no atomics).
    uint4* __restrict__ dst =
        reinterpret_cast<uint4*>(&g_partials[blockIdx.x * NWORDS]);
    const uint4* __restrict__ src = reinterpret_cast<const uint4*>(sh);
    #pragma unroll
    for (int i = threadIdx.x; i < NWORDS / 4; i += HIST_THREADS) dst[i] = src[i];
}

// ---------------------------------------------------------------------------
// Kernel 2: combine partials -> g_C. One thread per packed word; sums the
// lo/hi 16-bit halves across all HIST_BLOCKS partials. Fully overwrites g_C.
// ---------------------------------------------------------------------------
__global__ void combine_kernel() {
    int w = blockIdx.x * blockDim.x + threadIdx.x;
    if (w >= NWORDS) return;
    unsigned int lo = 0, hi = 0;
    #pragma unroll 16
    for (int k = 0; k < HIST_BLOCKS; k++) {
        unsigned int v = g_partials[k * NWORDS + w];
        lo += v & 0xFFFFu;
        hi += v >> 16;
    }
    reinterpret_cast<int2*>(g_C)[w] = make_int2((int)lo, (int)hi);
}

// ---------------------------------------------------------------------------
// Kernel 3: reduction + greedy matching. One block, 256 threads; thread t
// owns gt-row t and pred-column t.
//
// Majority-match identity: if 2*C[g][p] > gt_size[g] then C[g][p] exceeds
// half the row total, so it is the unique row maximum over p>=1. Hence the
// reference's argmax-of-M equals argmax of the row (cols 1..255), validated
// once by 2*maxv > gt_size. This removes the serial dependent scan; the row
// pass is int4-vectorized (64 loads, full MLP).
// ---------------------------------------------------------------------------
__global__ void reduce_kernel(float* __restrict__ out) {
    __shared__ int sh_gt_size[L];
    __shared__ int sh_pred_size[L];
    __shared__ int sh_colcnt[L];
    __shared__ int sh_best_p[L];
    __shared__ int sh_inter[L];
    __shared__ unsigned char sh_has[L];

    int t = threadIdx.x;  // 0..255

    // Row pass: sum (all cols) + max/argmax (cols 1..255), int4-vectorized.
    const int4* __restrict__ row = reinterpret_cast<const int4*>(&g_C[t * L]);
    int rs = 0, maxv = -1, bp = 0;
    #pragma unroll 8
    for (int i = 0; i < L / 4; i++) {
        int4 v = row[i];
        rs += v.x + v.y + v.z + v.w;
        int c = i * 4;
        if (c + 0 > 0 && v.x > maxv) { maxv = v.x; bp = c + 0; }
        if (v.y > maxv)              { maxv = v.y; bp = c + 1; }
        if (v.z > maxv)              { maxv = v.z; bp = c + 2; }
        if (v.w > maxv)              { maxv = v.w; bp = c + 3; }
    }
    sh_gt_size[t] = rs;

    // Column pass: sum (all rows) + Cnz>0 count (rows 1..255), unrolled MLP.
    int cs = 0, cc = 0;
    #pragma unroll 8
    for (int g = 0; g < L; g++) {
        int v = g_C[g * L + t];
        cs += v;
        if (g > 0 && v > 0) cc++;
    }
    sh_pred_size[t] = cs;
    sh_colcnt[t] = (t > 0) ? cc : 0;

    int hv = (t > 0) && (2 * maxv > rs);
    sh_best_p[t] = hv ? bp : 0;
    sh_has[t] = (unsigned char)hv;
    sh_inter[t] = hv ? maxv : 0;
    __syncthreads();

    if (t == 0) {
        int num_gt = 0, num_pred = 0, pairs = 0, ea = 0;
        for (int i = 1; i < L; i++) {
            if (sh_gt_size[i] > 0) num_gt++;
            if (sh_pred_size[i] > 0) num_pred++;
            pairs += sh_colcnt[i];
            if (sh_colcnt[i] > 1) ea++;
        }

        // Greedy matching in ascending gt-label order; a pred matches once.
        // Sequential by construction (matches jax.lax.scan accumulation order).
        bool used[L];
        for (int i = 0; i < L; i++) used[i] = false;
        int tp = 0;
        float seg_sum = 0.0f;
        for (int g = 1; g < L; g++) {
            int pl = sh_best_p[g];
            bool ok = sh_has[g] && !used[pl];
            if (ok) {
                int uni = sh_gt_size[g] + sh_pred_size[pl] - sh_inter[g];
                if (uni < 1) uni = 1;
                seg_sum += (float)sh_inter[g] / (float)uni;
                used[pl] = true;
                tp++;
            }
        }

        int ngi = num_gt > 0 ? num_gt : 1;
        float ng = (float)ngi;
        float seg = seg_sum / ng;
        int ns = pairs - tp;
        int fn = num_gt - tp;
        int fp = num_pred - tp;
        float det = 1.0f - (float)(fp + fn + ns + ea) / ng;

        bool both_empty = (num_gt == 0) && (num_pred == 0);
        bool any_empty = (num_gt == 0) || (num_pred == 0);
        if (both_empty)      { seg = 1.0f; det = 1.0f; }
        else if (any_empty)  { seg = 0.0f; det = 0.0f; }

        out[0] = seg;
        out[1] = det;
    }
}

// ---------------------------------------------------------------------------
extern "C" void kernel_launch(void* const* d_in, const int* in_sizes, int n_in,
                              void* d_out, int out_size) {
    const int* pred = (const int*)d_in[0];  // pred_labels_mask
    const int* gt   = (const int*)d_in[1];  // gt_labels_mask
    float* out = (float*)d_out;

    int n = in_sizes[0];  // 16,777,216
    int n4 = n / 4;

    cudaFuncSetAttribute(hist_kernel,
                         cudaFuncAttributeMaxDynamicSharedMemorySize,
                         SMEM_BYTES);

    hist_kernel<<<HIST_BLOCKS, HIST_THREADS, SMEM_BYTES>>>(pred, gt, n4);
    combine_kernel<<<(NWORDS + 255) / 256, 256>>>();
    reduce_kernel<<<1, L>>>(out);
}